// round 2
// baseline (speedup 1.0000x reference)
#include <cuda_runtime.h>
#include <math.h>

// ---------------------------------------------------------------------------
// Problem constants
// ---------------------------------------------------------------------------
#define NP 50000   // n_paper
#define ND 5000    // n_dataset
#define FD 512     // feature / hidden dim

// ---------------------------------------------------------------------------
// Scratch layout inside one big __device__ array (no allocations allowed)
// ---------------------------------------------------------------------------
constexpr size_t OFF_SUM_PP = 0;
constexpr size_t OFF_SUM_DP = OFF_SUM_PP + (size_t)NP * FD;
constexpr size_t OFF_SUM_PD = OFF_SUM_DP + (size_t)NP * FD;
constexpr size_t OFF_CNT_PP = OFF_SUM_PD + (size_t)ND * FD;
constexpr size_t OFF_CNT_DP = OFF_CNT_PP + NP;
constexpr size_t OFF_CNT_PD = OFF_CNT_DP + NP;
constexpr size_t ZERO_COUNT = OFF_CNT_PD + ND;          // region zeroed each call
constexpr size_t OFF_INV_PP = ZERO_COUNT;
constexpr size_t OFF_INV_DP = OFF_INV_PP + NP;
constexpr size_t OFF_INV_PD = OFF_INV_DP + NP;
constexpr size_t OFF_REC_P  = OFF_INV_PD + ND;
constexpr size_t OFF_REC_D  = OFF_REC_P + (size_t)NP * FD;
constexpr size_t OFF_XN_P   = OFF_REC_D + (size_t)ND * FD;
constexpr size_t OFF_XN_D   = OFF_XN_P + (size_t)NP * FD;
constexpr size_t OFF_WCOMB  = OFF_XN_D + (size_t)ND * FD;
constexpr size_t TOTAL_SCRATCH = OFF_WCOMB + (size_t)FD * FD;

__device__ float g_scratch[TOTAL_SCRATCH];

// ---------------------------------------------------------------------------
// Zero kernel (float4 grid-stride)
// ---------------------------------------------------------------------------
__global__ void zero_kernel(float4* p, size_t n4) {
    size_t i = (size_t)blockIdx.x * blockDim.x + threadIdx.x;
    size_t stride = (size_t)gridDim.x * blockDim.x;
    for (; i < n4; i += stride) p[i] = make_float4(0.f, 0.f, 0.f, 0.f);
}

// Wcomb = Wl_pp + Wl_dp (both multiply x_paper -> fold into one GEMM segment)
__global__ void addw_kernel(const float* __restrict__ a,
                            const float* __restrict__ b,
                            float* __restrict__ o) {
    int i = blockIdx.x * blockDim.x + threadIdx.x;
    if (i < FD * FD) o[i] = a[i] + b[i];
}

// ---------------------------------------------------------------------------
// Scatter-sum over edges: sum[dst] += x_src[src]; cnt[dst] += 1
// NOTE: edge indices are int32 on the wire (JAX x64 disabled downcasts int64).
// 128 threads per edge, 2 edges per 256-thread block, float4 gathers.
// ---------------------------------------------------------------------------
__global__ void scatter_kernel(const int* __restrict__ ei, int E,
                               const float* __restrict__ xsrc,
                               float* __restrict__ sum,
                               float* __restrict__ cnt) {
    int e = blockIdx.x * 2 + (threadIdx.x >> 7);
    if (e >= E) return;
    int lane = threadIdx.x & 127;
    int src = ei[e];
    int dst = ei[(size_t)E + e];
    float4 v = *(const float4*)(xsrc + (size_t)src * FD + lane * 4);
    float* o = sum + (size_t)dst * FD + lane * 4;
    atomicAdd(o + 0, v.x);
    atomicAdd(o + 1, v.y);
    atomicAdd(o + 2, v.z);
    atomicAdd(o + 3, v.w);
    if (lane == 0) atomicAdd(cnt + dst, 1.0f);
}

__global__ void inv_kernel(const float* __restrict__ cnt,
                           float* __restrict__ inv, int n) {
    int i = blockIdx.x * blockDim.x + threadIdx.x;
    if (i < n) inv[i] = 1.0f / fmaxf(cnt[i], 1.0f);
}

// ---------------------------------------------------------------------------
// Multi-segment SGEMM: C[M,512] = sum_s (scale_s(row) * A_s) @ B_s^T + bias1(+bias2)
//   A_s : [M,512] row-major, optional per-row scale (for mean aggregation)
//   B_s : weight rows [512 out, K=512 in], row stride ldb (1024 for decoder)
// Tiling: 128x128x8, 256 threads, 8x8 accumulators / thread.
// ---------------------------------------------------------------------------
struct Seg3 {
    const float* A[3];
    const float* scale[3];
    const float* B[3];
    int ldb[3];
};

__global__ __launch_bounds__(256) void gemm_kernel(
    Seg3 segs, int nseg,
    const float* __restrict__ bias1, const float* __restrict__ bias2,
    float* __restrict__ C, int M) {
    __shared__ float As[8][128];
    __shared__ float Bs[8][128];

    const int bm = blockIdx.x * 128;
    const int bn = blockIdx.y * 128;
    const int tid = threadIdx.x;
    const int tr = (tid / 16) * 8;      // output row offset within tile
    const int tc = (tid % 16) * 8;      // output col offset within tile
    const int lrow = tid >> 1;          // load row (0..127)
    const int lcol = (tid & 1) * 4;     // load col (0 or 4)

    float acc[8][8];
#pragma unroll
    for (int i = 0; i < 8; i++)
#pragma unroll
        for (int j = 0; j < 8; j++) acc[i][j] = 0.f;

    const int arow_g = bm + lrow;
    const bool arow_ok = (arow_g < M);

    for (int s = 0; s < nseg; s++) {
        const float* A = segs.A[s];
        const float* B = segs.B[s];
        const float* sc = segs.scale[s];
        const int ldb = segs.ldb[s];
        float rs = 1.0f;
        if (sc != nullptr && arow_ok) rs = sc[arow_g];
        const float* Arow = A + (size_t)arow_g * FD + lcol;
        const float* Brow = B + (size_t)(bn + lrow) * ldb + lcol;

        for (int kb = 0; kb < FD; kb += 8) {
            float4 a4 = arow_ok ? *(const float4*)(Arow + kb)
                                : make_float4(0.f, 0.f, 0.f, 0.f);
            float4 b4 = *(const float4*)(Brow + kb);
            As[lcol + 0][lrow] = a4.x * rs;
            As[lcol + 1][lrow] = a4.y * rs;
            As[lcol + 2][lrow] = a4.z * rs;
            As[lcol + 3][lrow] = a4.w * rs;
            Bs[lcol + 0][lrow] = b4.x;
            Bs[lcol + 1][lrow] = b4.y;
            Bs[lcol + 2][lrow] = b4.z;
            Bs[lcol + 3][lrow] = b4.w;
            __syncthreads();
#pragma unroll
            for (int k = 0; k < 8; k++) {
                float ra[8], rb[8];
#pragma unroll
                for (int i = 0; i < 8; i++) ra[i] = As[k][tr + i];
#pragma unroll
                for (int j = 0; j < 8; j++) rb[j] = Bs[k][tc + j];
#pragma unroll
                for (int i = 0; i < 8; i++)
#pragma unroll
                    for (int j = 0; j < 8; j++)
                        acc[i][j] = fmaf(ra[i], rb[j], acc[i][j]);
            }
            __syncthreads();
        }
    }

#pragma unroll
    for (int i = 0; i < 8; i++) {
        int r = bm + tr + i;
        if (r >= M) continue;
#pragma unroll
        for (int j = 0; j < 8; j += 4) {
            int c = bn + tc + j;
            float4 v;
            v.x = acc[i][j + 0] + bias1[c + 0] + (bias2 ? bias2[c + 0] : 0.f);
            v.y = acc[i][j + 1] + bias1[c + 1] + (bias2 ? bias2[c + 1] : 0.f);
            v.z = acc[i][j + 2] + bias1[c + 2] + (bias2 ? bias2[c + 2] : 0.f);
            v.w = acc[i][j + 3] + bias1[c + 3] + (bias2 ? bias2[c + 3] : 0.f);
            *(float4*)(C + (size_t)r * FD + c) = v;
        }
    }
}

// ---------------------------------------------------------------------------
// L2 normalize rows of [M,512]: one warp per row (matches F.normalize eps)
// ---------------------------------------------------------------------------
__global__ void l2norm_kernel(const float* __restrict__ in,
                              float* __restrict__ out, int M) {
    int warp = (int)(((size_t)blockIdx.x * blockDim.x + threadIdx.x) >> 5);
    if (warp >= M) return;
    int lane = threadIdx.x & 31;
    const float4* p = (const float4*)(in + (size_t)warp * FD);
    float4 v[4];
    float ss = 0.f;
#pragma unroll
    for (int i = 0; i < 4; i++) {
        v[i] = p[lane + 32 * i];
        ss += v[i].x * v[i].x + v[i].y * v[i].y + v[i].z * v[i].z + v[i].w * v[i].w;
    }
#pragma unroll
    for (int o = 16; o > 0; o >>= 1) ss += __shfl_xor_sync(0xffffffffu, ss, o);
    float inv = 1.0f / fmaxf(sqrtf(ss), 1e-12f);
    float4* q = (float4*)(out + (size_t)warp * FD);
#pragma unroll
    for (int i = 0; i < 4; i++) {
        float4 w = v[i];
        w.x *= inv; w.y *= inv; w.z *= inv; w.w *= inv;
        q[lane + 32 * i] = w;
    }
}

// ---------------------------------------------------------------------------
// kernel_launch
// ---------------------------------------------------------------------------
extern "C" void kernel_launch(void* const* d_in, const int* in_sizes, int n_in,
                              void* d_out, int out_size) {
    const float* x_paper   = (const float*)d_in[0];
    const float* x_dataset = (const float*)d_in[1];
    const int*   ei_pp     = (const int*)d_in[2];
    const int*   ei_pd     = (const int*)d_in[3];
    const int*   ei_dp     = (const int*)d_in[4];
    const float* Wl_pp = (const float*)d_in[5];
    const float* Wr_pp = (const float*)d_in[6];
    const float* b_pp  = (const float*)d_in[7];
    const float* Wl_pd = (const float*)d_in[8];
    const float* Wr_pd = (const float*)d_in[9];
    const float* b_pd  = (const float*)d_in[10];
    const float* Wl_dp = (const float*)d_in[11];
    const float* Wr_dp = (const float*)d_in[12];
    const float* b_dp  = (const float*)d_in[13];
    const float* Wdec_p = (const float*)d_in[14];
    const float* bdec_p = (const float*)d_in[15];
    const float* Wdec_d = (const float*)d_in[16];
    const float* bdec_d = (const float*)d_in[17];

    const int Epp = in_sizes[2] / 2;
    const int Epd = in_sizes[3] / 2;
    const int Edp = in_sizes[4] / 2;

    float* out = (float*)d_out;

    float* base = nullptr;
    cudaGetSymbolAddress((void**)&base, g_scratch);
    float* sum_pp = base + OFF_SUM_PP;
    float* sum_dp = base + OFF_SUM_DP;
    float* sum_pd = base + OFF_SUM_PD;
    float* cnt_pp = base + OFF_CNT_PP;
    float* cnt_dp = base + OFF_CNT_DP;
    float* cnt_pd = base + OFF_CNT_PD;
    float* inv_pp = base + OFF_INV_PP;
    float* inv_dp = base + OFF_INV_DP;
    float* inv_pd = base + OFF_INV_PD;
    float* rec_p  = base + OFF_REC_P;
    float* rec_d  = base + OFF_REC_D;
    float* xn_p   = base + OFF_XN_P;
    float* xn_d   = base + OFF_XN_D;
    float* wcomb  = base + OFF_WCOMB;

    // 1) zero sums + counts
    zero_kernel<<<8192, 256>>>((float4*)base, ZERO_COUNT / 4);

    // 2) combined self weight for paper (Wl_pp + Wl_dp)
    addw_kernel<<<(FD * FD + 255) / 256, 256>>>(Wl_pp, Wl_dp, wcomb);

    // 3) scatter-sum per edge type
    scatter_kernel<<<(Epp + 1) / 2, 256>>>(ei_pp, Epp, x_paper,   sum_pp, cnt_pp);
    scatter_kernel<<<(Edp + 1) / 2, 256>>>(ei_dp, Edp, x_dataset, sum_dp, cnt_dp);
    scatter_kernel<<<(Epd + 1) / 2, 256>>>(ei_pd, Epd, x_paper,   sum_pd, cnt_pd);

    // 4) reciprocal counts (mean folded into GEMM A-load)
    inv_kernel<<<(NP + 255) / 256, 256>>>(cnt_pp, inv_pp, NP);
    inv_kernel<<<(NP + 255) / 256, 256>>>(cnt_dp, inv_dp, NP);
    inv_kernel<<<(ND + 255) / 256, 256>>>(cnt_pd, inv_pd, ND);

    dim3 gp((NP + 127) / 128, FD / 128);
    dim3 gd((ND + 127) / 128, FD / 128);

    // 5) rec_paper = mean_pp@Wr_pp^T + mean_dp@Wr_dp^T + x_paper@Wcomb^T + b_pp + b_dp
    Seg3 sp = {};
    sp.A[0] = sum_pp;  sp.scale[0] = inv_pp;  sp.B[0] = Wr_pp; sp.ldb[0] = FD;
    sp.A[1] = sum_dp;  sp.scale[1] = inv_dp;  sp.B[1] = Wr_dp; sp.ldb[1] = FD;
    sp.A[2] = x_paper; sp.scale[2] = nullptr; sp.B[2] = wcomb; sp.ldb[2] = FD;
    gemm_kernel<<<gp, 256>>>(sp, 3, b_pp, b_dp, rec_p, NP);

    // 6) rec_dataset = mean_pd@Wr_pd^T + x_dataset@Wl_pd^T + b_pd
    Seg3 sd = {};
    sd.A[0] = sum_pd;    sd.scale[0] = inv_pd;  sd.B[0] = Wr_pd; sd.ldb[0] = FD;
    sd.A[1] = x_dataset; sd.scale[1] = nullptr; sd.B[1] = Wl_pd; sd.ldb[1] = FD;
    gemm_kernel<<<gd, 256>>>(sd, 2, b_pd, nullptr, rec_d, ND);

    // 7) L2 norms
    l2norm_kernel<<<(NP * 32 + 255) / 256, 256>>>(rec_p, rec_p, NP);
    l2norm_kernel<<<(NP * 32 + 255) / 256, 256>>>(x_paper, xn_p, NP);
    l2norm_kernel<<<(ND * 32 + 255) / 256, 256>>>(rec_d, rec_d, ND);
    l2norm_kernel<<<(ND * 32 + 255) / 256, 256>>>(x_dataset, xn_d, ND);

    // 8) decoder: out = [rec_n, xn] @ Wdec^T + bdec  (split K into two 512 segments)
    Seg3 dpS = {};
    dpS.A[0] = rec_p; dpS.scale[0] = nullptr; dpS.B[0] = Wdec_p;       dpS.ldb[0] = 2 * FD;
    dpS.A[1] = xn_p;  dpS.scale[1] = nullptr; dpS.B[1] = Wdec_p + FD;  dpS.ldb[1] = 2 * FD;
    gemm_kernel<<<gp, 256>>>(dpS, 2, bdec_p, nullptr, out, NP);

    Seg3 ddS = {};
    ddS.A[0] = rec_d; ddS.scale[0] = nullptr; ddS.B[0] = Wdec_d;       ddS.ldb[0] = 2 * FD;
    ddS.A[1] = xn_d;  ddS.scale[1] = nullptr; ddS.B[1] = Wdec_d + FD;  ddS.ldb[1] = 2 * FD;
    gemm_kernel<<<gd, 256>>>(ddS, 2, bdec_d, nullptr, out + (size_t)NP * FD, ND);
}

// round 3
// speedup vs baseline: 2.2807x; 2.2807x over previous
#include <cuda_runtime.h>
#include <math.h>

// ---------------------------------------------------------------------------
// Problem constants
// ---------------------------------------------------------------------------
#define NP 50000   // n_paper
#define ND 5000    // n_dataset
#define FD 512     // feature / hidden dim

// ---------------------------------------------------------------------------
// Scratch layout inside one big __device__ array (no allocations allowed)
// ---------------------------------------------------------------------------
constexpr size_t OFF_SUM_PP = 0;
constexpr size_t OFF_SUM_DP = OFF_SUM_PP + (size_t)NP * FD;
constexpr size_t OFF_SUM_PD = OFF_SUM_DP + (size_t)NP * FD;
constexpr size_t OFF_CNT_PP = OFF_SUM_PD + (size_t)ND * FD;
constexpr size_t OFF_CNT_DP = OFF_CNT_PP + NP;
constexpr size_t OFF_CNT_PD = OFF_CNT_DP + NP;
constexpr size_t ZERO_COUNT = OFF_CNT_PD + ND;          // region zeroed each call
constexpr size_t OFF_INV_PP = ZERO_COUNT;
constexpr size_t OFF_INV_DP = OFF_INV_PP + NP;
constexpr size_t OFF_INV_PD = OFF_INV_DP + NP;
constexpr size_t OFF_REC_P  = OFF_INV_PD + ND;
constexpr size_t OFF_REC_D  = OFF_REC_P + (size_t)NP * FD;
constexpr size_t OFF_XN_P   = OFF_REC_D + (size_t)ND * FD;
constexpr size_t OFF_XN_D   = OFF_XN_P + (size_t)NP * FD;
constexpr size_t OFF_WCOMB  = OFF_XN_D + (size_t)ND * FD;
constexpr size_t TOTAL_SCRATCH = OFF_WCOMB + (size_t)FD * FD;

__device__ float g_scratch[TOTAL_SCRATCH];

// ---------------------------------------------------------------------------
// Zero kernel (float4 grid-stride)
// ---------------------------------------------------------------------------
__global__ void zero_kernel(float4* p, size_t n4) {
    size_t i = (size_t)blockIdx.x * blockDim.x + threadIdx.x;
    size_t stride = (size_t)gridDim.x * blockDim.x;
    for (; i < n4; i += stride) p[i] = make_float4(0.f, 0.f, 0.f, 0.f);
}

// Wcomb = Wl_pp + Wl_dp (both multiply x_paper -> fold into one GEMM segment)
__global__ void addw_kernel(const float* __restrict__ a,
                            const float* __restrict__ b,
                            float* __restrict__ o) {
    int i = blockIdx.x * blockDim.x + threadIdx.x;
    if (i < FD * FD) o[i] = a[i] + b[i];
}

// ---------------------------------------------------------------------------
// Scatter-sum over edges: sum[dst] += x_src[src]; cnt[dst] += 1
// (edge indices are int32 on the wire)
// ---------------------------------------------------------------------------
__global__ void scatter_kernel(const int* __restrict__ ei, int E,
                               const float* __restrict__ xsrc,
                               float* __restrict__ sum,
                               float* __restrict__ cnt) {
    int e = blockIdx.x * 2 + (threadIdx.x >> 7);
    if (e >= E) return;
    int lane = threadIdx.x & 127;
    int src = ei[e];
    int dst = ei[(size_t)E + e];
    float4 v = *(const float4*)(xsrc + (size_t)src * FD + lane * 4);
    float* o = sum + (size_t)dst * FD + lane * 4;
    atomicAdd(o + 0, v.x);
    atomicAdd(o + 1, v.y);
    atomicAdd(o + 2, v.z);
    atomicAdd(o + 3, v.w);
    if (lane == 0) atomicAdd(cnt + dst, 1.0f);
}

__global__ void inv_kernel(const float* __restrict__ cnt,
                           float* __restrict__ inv, int n) {
    int i = blockIdx.x * blockDim.x + threadIdx.x;
    if (i < n) inv[i] = 1.0f / fmaxf(cnt[i], 1.0f);
}

// ---------------------------------------------------------------------------
// tf32 tensor-core multi-segment GEMM:
//   C[M,512] = sum_s (scale_s(row) * A_s) @ B_s^T + bias1 (+bias2)
// Tiles: block 128x128x32, 8 warps (2x4), warp tile 64x32 via m16n8k8 tf32.
// Smem K-major with +8 padding -> fragment loads hit all 32 banks.
// ---------------------------------------------------------------------------
struct Seg3 {
    const float* A[3];
    const float* scale[3];
    const float* B[3];
    int ldb[3];
};

__device__ __forceinline__ unsigned f2tf(float x) {
    unsigned r;
    asm("cvt.rna.tf32.f32 %0, %1;" : "=r"(r) : "f"(x));
    return r;
}

#define BM 128
#define BN 128
#define BK 32
#define SPAD 8

__global__ __launch_bounds__(256, 2) void gemm_tc(
    Seg3 segs, int nseg,
    const float* __restrict__ bias1, const float* __restrict__ bias2,
    float* __restrict__ C, int M) {
    __shared__ unsigned As[BK][BM + SPAD];
    __shared__ unsigned Bs[BK][BN + SPAD];

    const int tid  = threadIdx.x;
    const int lane = tid & 31;
    const int warp = tid >> 5;
    const int wm = warp >> 2;          // 0..1 (M dir)
    const int wn = warp & 3;           // 0..3 (N dir)
    const int bm = blockIdx.x * BM;
    const int bn = blockIdx.y * BN;

    const int lr = tid >> 1;           // load row 0..127
    const int lk = (tid & 1) * 16;     // k offset 0/16

    const int g  = lane >> 2;          // group id 0..7
    const int t4 = lane & 3;           // 0..3

    float acc[4][4][4];
#pragma unroll
    for (int i = 0; i < 4; i++)
#pragma unroll
        for (int j = 0; j < 4; j++)
#pragma unroll
            for (int r = 0; r < 4; r++) acc[i][j][r] = 0.f;

    const int arow = bm + lr;
    const bool aok = (arow < M);

    for (int s = 0; s < nseg; s++) {
        const float* A  = segs.A[s];
        const float* B  = segs.B[s];
        const float* sc = segs.scale[s];
        const int ldb   = segs.ldb[s];
        float rs = 1.0f;
        if (sc != nullptr && aok) rs = sc[arow];
        const float* Ap = A + (size_t)arow * FD + lk;
        const float* Bp = B + (size_t)(bn + lr) * ldb + lk;

        for (int kb = 0; kb < FD; kb += BK) {
            // stage global tile in regs (MLP=8)
            float4 av[4], bv[4];
#pragma unroll
            for (int v = 0; v < 4; v++)
                av[v] = aok ? *(const float4*)(Ap + kb + v * 4)
                            : make_float4(0.f, 0.f, 0.f, 0.f);
#pragma unroll
            for (int v = 0; v < 4; v++)
                bv[v] = *(const float4*)(Bp + kb + v * 4);

            __syncthreads();   // previous tile fully consumed
#pragma unroll
            for (int v = 0; v < 4; v++) {
                int k = lk + v * 4;
                As[k + 0][lr] = f2tf(av[v].x * rs);
                As[k + 1][lr] = f2tf(av[v].y * rs);
                As[k + 2][lr] = f2tf(av[v].z * rs);
                As[k + 3][lr] = f2tf(av[v].w * rs);
                Bs[k + 0][lr] = f2tf(bv[v].x);
                Bs[k + 1][lr] = f2tf(bv[v].y);
                Bs[k + 2][lr] = f2tf(bv[v].z);
                Bs[k + 3][lr] = f2tf(bv[v].w);
            }
            __syncthreads();

#pragma unroll
            for (int ks = 0; ks < BK / 8; ks++) {
                const int k0 = ks * 8 + t4;
                unsigned a[4][4], b[4][2];
                const int m0 = wm * 64 + g;
#pragma unroll
                for (int mi = 0; mi < 4; mi++) {
                    a[mi][0] = As[k0][m0 + mi * 16];
                    a[mi][1] = As[k0][m0 + mi * 16 + 8];
                    a[mi][2] = As[k0 + 4][m0 + mi * 16];
                    a[mi][3] = As[k0 + 4][m0 + mi * 16 + 8];
                }
                const int n0 = wn * 32 + g;
#pragma unroll
                for (int ni = 0; ni < 4; ni++) {
                    b[ni][0] = Bs[k0][n0 + ni * 8];
                    b[ni][1] = Bs[k0 + 4][n0 + ni * 8];
                }
#pragma unroll
                for (int mi = 0; mi < 4; mi++)
#pragma unroll
                    for (int ni = 0; ni < 4; ni++) {
                        asm volatile(
                            "mma.sync.aligned.m16n8k8.row.col.f32.tf32.tf32.f32 "
                            "{%0,%1,%2,%3}, {%4,%5,%6,%7}, {%8,%9}, {%0,%1,%2,%3};"
                            : "+f"(acc[mi][ni][0]), "+f"(acc[mi][ni][1]),
                              "+f"(acc[mi][ni][2]), "+f"(acc[mi][ni][3])
                            : "r"(a[mi][0]), "r"(a[mi][1]), "r"(a[mi][2]),
                              "r"(a[mi][3]), "r"(b[ni][0]), "r"(b[ni][1]));
                    }
            }
        }
        __syncthreads();  // before next segment overwrites smem (loop top also syncs)
    }

    // epilogue: bias add + store (float2 per c-pair)
#pragma unroll
    for (int ni = 0; ni < 4; ni++) {
        const int c = bn + wn * 32 + ni * 8 + t4 * 2;
        float bb0 = bias1[c] + (bias2 ? bias2[c] : 0.f);
        float bb1 = bias1[c + 1] + (bias2 ? bias2[c + 1] : 0.f);
#pragma unroll
        for (int mi = 0; mi < 4; mi++) {
            const int r0 = bm + wm * 64 + mi * 16 + g;
            if (r0 < M) {
                float2 v0 = make_float2(acc[mi][ni][0] + bb0, acc[mi][ni][1] + bb1);
                *(float2*)(C + (size_t)r0 * FD + c) = v0;
            }
            const int r1 = r0 + 8;
            if (r1 < M) {
                float2 v1 = make_float2(acc[mi][ni][2] + bb0, acc[mi][ni][3] + bb1);
                *(float2*)(C + (size_t)r1 * FD + c) = v1;
            }
        }
    }
}

// ---------------------------------------------------------------------------
// L2 normalize rows of [M,512]: one warp per row (matches F.normalize eps)
// ---------------------------------------------------------------------------
__global__ void l2norm_kernel(const float* __restrict__ in,
                              float* __restrict__ out, int M) {
    int warp = (int)(((size_t)blockIdx.x * blockDim.x + threadIdx.x) >> 5);
    if (warp >= M) return;
    int lane = threadIdx.x & 31;
    const float4* p = (const float4*)(in + (size_t)warp * FD);
    float4 v[4];
    float ss = 0.f;
#pragma unroll
    for (int i = 0; i < 4; i++) {
        v[i] = p[lane + 32 * i];
        ss += v[i].x * v[i].x + v[i].y * v[i].y + v[i].z * v[i].z + v[i].w * v[i].w;
    }
#pragma unroll
    for (int o = 16; o > 0; o >>= 1) ss += __shfl_xor_sync(0xffffffffu, ss, o);
    float inv = 1.0f / fmaxf(sqrtf(ss), 1e-12f);
    float4* q = (float4*)(out + (size_t)warp * FD);
#pragma unroll
    for (int i = 0; i < 4; i++) {
        float4 w = v[i];
        w.x *= inv; w.y *= inv; w.z *= inv; w.w *= inv;
        q[lane + 32 * i] = w;
    }
}

// ---------------------------------------------------------------------------
// kernel_launch
// ---------------------------------------------------------------------------
extern "C" void kernel_launch(void* const* d_in, const int* in_sizes, int n_in,
                              void* d_out, int out_size) {
    const float* x_paper   = (const float*)d_in[0];
    const float* x_dataset = (const float*)d_in[1];
    const int*   ei_pp     = (const int*)d_in[2];
    const int*   ei_pd     = (const int*)d_in[3];
    const int*   ei_dp     = (const int*)d_in[4];
    const float* Wl_pp = (const float*)d_in[5];
    const float* Wr_pp = (const float*)d_in[6];
    const float* b_pp  = (const float*)d_in[7];
    const float* Wl_pd = (const float*)d_in[8];
    const float* Wr_pd = (const float*)d_in[9];
    const float* b_pd  = (const float*)d_in[10];
    const float* Wl_dp = (const float*)d_in[11];
    const float* Wr_dp = (const float*)d_in[12];
    const float* b_dp  = (const float*)d_in[13];
    const float* Wdec_p = (const float*)d_in[14];
    const float* bdec_p = (const float*)d_in[15];
    const float* Wdec_d = (const float*)d_in[16];
    const float* bdec_d = (const float*)d_in[17];

    const int Epp = in_sizes[2] / 2;
    const int Epd = in_sizes[3] / 2;
    const int Edp = in_sizes[4] / 2;

    float* out = (float*)d_out;

    float* base = nullptr;
    cudaGetSymbolAddress((void**)&base, g_scratch);
    float* sum_pp = base + OFF_SUM_PP;
    float* sum_dp = base + OFF_SUM_DP;
    float* sum_pd = base + OFF_SUM_PD;
    float* cnt_pp = base + OFF_CNT_PP;
    float* cnt_dp = base + OFF_CNT_DP;
    float* cnt_pd = base + OFF_CNT_PD;
    float* inv_pp = base + OFF_INV_PP;
    float* inv_dp = base + OFF_INV_DP;
    float* inv_pd = base + OFF_INV_PD;
    float* rec_p  = base + OFF_REC_P;
    float* rec_d  = base + OFF_REC_D;
    float* xn_p   = base + OFF_XN_P;
    float* xn_d   = base + OFF_XN_D;
    float* wcomb  = base + OFF_WCOMB;

    // 1) zero sums + counts
    zero_kernel<<<8192, 256>>>((float4*)base, ZERO_COUNT / 4);

    // 2) combined self weight for paper (Wl_pp + Wl_dp)
    addw_kernel<<<(FD * FD + 255) / 256, 256>>>(Wl_pp, Wl_dp, wcomb);

    // 3) scatter-sum per edge type
    scatter_kernel<<<(Epp + 1) / 2, 256>>>(ei_pp, Epp, x_paper,   sum_pp, cnt_pp);
    scatter_kernel<<<(Edp + 1) / 2, 256>>>(ei_dp, Edp, x_dataset, sum_dp, cnt_dp);
    scatter_kernel<<<(Epd + 1) / 2, 256>>>(ei_pd, Epd, x_paper,   sum_pd, cnt_pd);

    // 4) reciprocal counts (mean folded into GEMM A-load)
    inv_kernel<<<(NP + 255) / 256, 256>>>(cnt_pp, inv_pp, NP);
    inv_kernel<<<(NP + 255) / 256, 256>>>(cnt_dp, inv_dp, NP);
    inv_kernel<<<(ND + 255) / 256, 256>>>(cnt_pd, inv_pd, ND);

    dim3 gp((NP + BM - 1) / BM, FD / BN);
    dim3 gd((ND + BM - 1) / BM, FD / BN);

    // 5) rec_paper = mean_pp@Wr_pp^T + mean_dp@Wr_dp^T + x_paper@Wcomb^T + b_pp + b_dp
    Seg3 sp = {};
    sp.A[0] = sum_pp;  sp.scale[0] = inv_pp;  sp.B[0] = Wr_pp; sp.ldb[0] = FD;
    sp.A[1] = sum_dp;  sp.scale[1] = inv_dp;  sp.B[1] = Wr_dp; sp.ldb[1] = FD;
    sp.A[2] = x_paper; sp.scale[2] = nullptr; sp.B[2] = wcomb; sp.ldb[2] = FD;
    gemm_tc<<<gp, 256>>>(sp, 3, b_pp, b_dp, rec_p, NP);

    // 6) rec_dataset = mean_pd@Wr_pd^T + x_dataset@Wl_pd^T + b_pd
    Seg3 sd = {};
    sd.A[0] = sum_pd;    sd.scale[0] = inv_pd;  sd.B[0] = Wr_pd; sd.ldb[0] = FD;
    sd.A[1] = x_dataset; sd.scale[1] = nullptr; sd.B[1] = Wl_pd; sd.ldb[1] = FD;
    gemm_tc<<<gd, 256>>>(sd, 2, b_pd, nullptr, rec_d, ND);

    // 7) L2 norms
    l2norm_kernel<<<(NP * 32 + 255) / 256, 256>>>(rec_p, rec_p, NP);
    l2norm_kernel<<<(NP * 32 + 255) / 256, 256>>>(x_paper, xn_p, NP);
    l2norm_kernel<<<(ND * 32 + 255) / 256, 256>>>(rec_d, rec_d, ND);
    l2norm_kernel<<<(ND * 32 + 255) / 256, 256>>>(x_dataset, xn_d, ND);

    // 8) decoder: out = [rec_n, xn] @ Wdec^T + bdec  (split K into two 512 segments)
    Seg3 dpS = {};
    dpS.A[0] = rec_p; dpS.scale[0] = nullptr; dpS.B[0] = Wdec_p;       dpS.ldb[0] = 2 * FD;
    dpS.A[1] = xn_p;  dpS.scale[1] = nullptr; dpS.B[1] = Wdec_p + FD;  dpS.ldb[1] = 2 * FD;
    gemm_tc<<<gp, 256>>>(dpS, 2, bdec_p, nullptr, out, NP);

    Seg3 ddS = {};
    ddS.A[0] = rec_d; ddS.scale[0] = nullptr; ddS.B[0] = Wdec_d;       ddS.ldb[0] = 2 * FD;
    ddS.A[1] = xn_d;  ddS.scale[1] = nullptr; ddS.B[1] = Wdec_d + FD;  ddS.ldb[1] = 2 * FD;
    gemm_tc<<<gd, 256>>>(ddS, 2, bdec_d, nullptr, out + (size_t)NP * FD, ND);
}

// round 4
// speedup vs baseline: 3.0351x; 1.3308x over previous
#include <cuda_runtime.h>
#include <math.h>

#define NP 50000
#define ND 5000
#define FD 512

// ---------------------------------------------------------------------------
// Scratch (u32 units). Sums are fp32 from atomics, converted to tf32 in place.
// ---------------------------------------------------------------------------
constexpr size_t U_SUM_PP = 0;
constexpr size_t U_SUM_DP = U_SUM_PP + (size_t)NP * FD;
constexpr size_t U_SUM_PD = U_SUM_DP + (size_t)NP * FD;
constexpr size_t U_CNT_PP = U_SUM_PD + (size_t)ND * FD;
constexpr size_t U_CNT_DP = U_CNT_PP + NP;
constexpr size_t U_CNT_PD = U_CNT_DP + NP;
constexpr size_t ZERO_END = U_CNT_PD + ND;
constexpr size_t U_XT_P   = ZERO_END;                       // tf32 x_paper
constexpr size_t U_XT_D   = U_XT_P + (size_t)NP * FD;       // tf32 x_dataset
constexpr size_t U_REC_P  = U_XT_D + (size_t)ND * FD;       // fp32 -> tf32 in place
constexpr size_t U_REC_D  = U_REC_P + (size_t)NP * FD;
constexpr size_t U_XNT_P  = U_REC_D + (size_t)ND * FD;      // tf32 l2norm(x_paper)
constexpr size_t U_XNT_D  = U_XNT_P + (size_t)NP * FD;
constexpr size_t U_WCOMB  = U_XNT_D + (size_t)ND * FD;
constexpr size_t U_WRPP   = U_WCOMB + (size_t)FD * FD;
constexpr size_t U_WRDP   = U_WRPP + (size_t)FD * FD;
constexpr size_t U_WRPD   = U_WRDP + (size_t)FD * FD;
constexpr size_t U_WLPD   = U_WRPD + (size_t)FD * FD;
constexpr size_t U_WDECP  = U_WLPD + (size_t)FD * FD;
constexpr size_t U_WDECD  = U_WDECP + (size_t)FD * 2 * FD;
constexpr size_t U_BSUM   = U_WDECD + (size_t)FD * 2 * FD;
constexpr size_t U_TOTAL  = U_BSUM + FD;

__device__ __align__(16) unsigned g_scratch[U_TOTAL];

__device__ __forceinline__ unsigned f2tf(float x) {
    unsigned r;
    asm("cvt.rna.tf32.f32 %0, %1;" : "=r"(r) : "f"(x));
    return r;
}

// ---------------------------------------------------------------------------
// small helpers
// ---------------------------------------------------------------------------
__global__ void zero_kernel(float4* p, size_t n4) {
    size_t i = (size_t)blockIdx.x * blockDim.x + threadIdx.x;
    size_t stride = (size_t)gridDim.x * blockDim.x;
    for (; i < n4; i += stride) p[i] = make_float4(0.f, 0.f, 0.f, 0.f);
}

__global__ void cvt_kernel(const float4* __restrict__ in,
                           uint4* __restrict__ out, int n4) {
    int i = blockIdx.x * blockDim.x + threadIdx.x;
    if (i >= n4) return;
    float4 v = in[i];
    out[i] = make_uint4(f2tf(v.x), f2tf(v.y), f2tf(v.z), f2tf(v.w));
}

__global__ void addcvt_kernel(const float* __restrict__ a,
                              const float* __restrict__ b,
                              unsigned* __restrict__ o, int n) {
    int i = blockIdx.x * blockDim.x + threadIdx.x;
    if (i < n) o[i] = f2tf(a[i] + b[i]);
}

__global__ void addbias_kernel(const float* __restrict__ a,
                               const float* __restrict__ b,
                               float* __restrict__ o) {
    int i = threadIdx.x + blockIdx.x * blockDim.x;
    if (i < FD) o[i] = a[i] + b[i];
}

// ---------------------------------------------------------------------------
// Scatter-sum with vector RED (sm_90+): sum[dst] += x_src[src]; cnt[dst] += 1
// ---------------------------------------------------------------------------
__global__ void scatter_kernel(const int* __restrict__ ei, int E,
                               const float* __restrict__ xsrc,
                               float* __restrict__ sum,
                               float* __restrict__ cnt) {
    int e = blockIdx.x * 2 + (threadIdx.x >> 7);
    if (e >= E) return;
    int lane = threadIdx.x & 127;
    int src = ei[e];
    int dst = ei[(size_t)E + e];
    float4 v = *(const float4*)(xsrc + (size_t)src * FD + lane * 4);
    float* o = sum + (size_t)dst * FD + lane * 4;
    asm volatile("red.global.add.v4.f32 [%0], {%1,%2,%3,%4};"
                 :: "l"(o), "f"(v.x), "f"(v.y), "f"(v.z), "f"(v.w) : "memory");
    if (lane == 0) atomicAdd(cnt + dst, 1.0f);
}

// finalize: sum[row][:] = tf32(sum[row][:] / max(cnt[row],1))  (in place)
__global__ void finalize_kernel(unsigned* __restrict__ s,
                                const float* __restrict__ cnt, int M) {
    size_t i = (size_t)blockIdx.x * blockDim.x + threadIdx.x;
    if (i >= (size_t)M * (FD / 4)) return;
    int row = (int)(i >> 7);
    float iv = 1.0f / fmaxf(cnt[row], 1.0f);
    float4 v = ((float4*)s)[i];
    ((uint4*)s)[i] = make_uint4(f2tf(v.x * iv), f2tf(v.y * iv),
                                f2tf(v.z * iv), f2tf(v.w * iv));
}

// l2-normalize rows -> tf32; optionally also emit plain tf32 copy.
// one warp per row; safe for in-place (row fully read before write).
__global__ void cvtnorm_kernel(const float* __restrict__ in,
                               unsigned* __restrict__ out_n,
                               unsigned* __restrict__ out_p, int M) {
    int row = (int)(((size_t)blockIdx.x * blockDim.x + threadIdx.x) >> 5);
    if (row >= M) return;
    int lane = threadIdx.x & 31;
    const float4* p = (const float4*)(in + (size_t)row * FD);
    float4 v[4];
    float ss = 0.f;
#pragma unroll
    for (int i = 0; i < 4; i++) {
        v[i] = p[lane + 32 * i];
        ss += v[i].x * v[i].x + v[i].y * v[i].y + v[i].z * v[i].z + v[i].w * v[i].w;
    }
#pragma unroll
    for (int o = 16; o > 0; o >>= 1) ss += __shfl_xor_sync(0xffffffffu, ss, o);
    float inv = 1.0f / fmaxf(sqrtf(ss), 1e-12f);
    if (out_p) {
        uint4* q = (uint4*)(out_p + (size_t)row * FD);
#pragma unroll
        for (int i = 0; i < 4; i++)
            q[lane + 32 * i] = make_uint4(f2tf(v[i].x), f2tf(v[i].y),
                                          f2tf(v[i].z), f2tf(v[i].w));
    }
    uint4* qn = (uint4*)(out_n + (size_t)row * FD);
#pragma unroll
    for (int i = 0; i < 4; i++)
        qn[lane + 32 * i] = make_uint4(f2tf(v[i].x * inv), f2tf(v[i].y * inv),
                                       f2tf(v[i].z * inv), f2tf(v[i].w * inv));
}

// ---------------------------------------------------------------------------
// tf32 tensor-core GEMM, cp.async 2-stage pipeline.
//   C[M,512] = sum_s A_s @ B_s^T + bias     (A_s,B_s pre-converted tf32 u32)
// block 128x256x32, 8 warps (2x4), warp tile 64x64 (m16n8k8).
// ---------------------------------------------------------------------------
struct SegU {
    const unsigned* A[3];
    const unsigned* B[3];
    int ldb[3];
};

#define BM 128
#define BN 256
#define BK 32
#define SROW 36                       // BK + 4 pad (u32), 144B rows (16B mult)
#define STAGE ((BM + BN) * SROW)      // u32 per stage

__device__ __forceinline__ void cp16(unsigned* dst, const unsigned* src, int sz) {
    unsigned d = (unsigned)__cvta_generic_to_shared(dst);
    asm volatile("cp.async.cg.shared.global [%0], [%1], 16, %2;"
                 :: "r"(d), "l"(src), "r"(sz));
}

extern __shared__ unsigned smem_u[];

__global__ __launch_bounds__(256, 1) void gemm_tc2(
    SegU segs, int nseg, const float* __restrict__ bias,
    float* __restrict__ C, int M) {
    const int tid  = threadIdx.x;
    const int lane = tid & 31;
    const int warp = tid >> 5;
    const int wm = warp >> 2;           // 0..1
    const int wn = warp & 3;            // 0..3
    const int bm = blockIdx.x * BM;
    const int bn = blockIdx.y * BN;
    const int g  = lane >> 2;
    const int t4 = lane & 3;

    const int crow = tid >> 3;          // 0..31
    const int ccol = (tid & 7) * 4;     // 0,4,...,28

    float acc[4][8][4];
#pragma unroll
    for (int mi = 0; mi < 4; mi++)
#pragma unroll
        for (int ni = 0; ni < 8; ni++)
#pragma unroll
            for (int r = 0; r < 4; r++) acc[mi][ni][r] = 0.f;

    const int NKB = nseg * (FD / BK);

    // --- async stage loader ---
    auto issue = [&](int kb, int st) {
        const int s = kb >> 4;
        const size_t koff = (size_t)((kb & 15) * BK + ccol);
        const unsigned* Ab = segs.A[s];
        const unsigned* Bb = segs.B[s];
        const int ldb = segs.ldb[s];
        unsigned* Ad = smem_u + st * STAGE + crow * SROW + ccol;
        unsigned* Bd = smem_u + st * STAGE + BM * SROW + crow * SROW + ccol;
#pragma unroll
        for (int i = 0; i < 4; i++) {
            int r = bm + crow + 32 * i;
            bool ok = r < M;
            cp16(Ad + 32 * i * SROW,
                 Ab + (size_t)(ok ? r : 0) * FD + koff, ok ? 16 : 0);
        }
#pragma unroll
        for (int i = 0; i < 8; i++) {
            int r = bn + crow + 32 * i;
            cp16(Bd + 32 * i * SROW, Bb + (size_t)r * ldb + koff, 16);
        }
        asm volatile("cp.async.commit_group;");
    };

    issue(0, 0);

    for (int kb = 0; kb < NKB; kb++) {
        const int st = kb & 1;
        if (kb + 1 < NKB) {
            issue(kb + 1, st ^ 1);
            asm volatile("cp.async.wait_group 1;");
        } else {
            asm volatile("cp.async.wait_group 0;");
        }
        __syncthreads();

        const unsigned* Ad = smem_u + st * STAGE;
        const unsigned* Bd = smem_u + st * STAGE + BM * SROW;

#pragma unroll
        for (int ks = 0; ks < BK / 8; ks++) {
            const int k0 = ks * 8 + t4;
            unsigned a[4][4], b[8][2];
            const int m0 = wm * 64 + g;
#pragma unroll
            for (int mi = 0; mi < 4; mi++) {
                const unsigned* r0 = Ad + (m0 + mi * 16) * SROW;
                a[mi][0] = r0[k0];
                a[mi][1] = r0[8 * SROW + k0];
                a[mi][2] = r0[k0 + 4];
                a[mi][3] = r0[8 * SROW + k0 + 4];
            }
            const int n0 = wn * 64 + g;
#pragma unroll
            for (int ni = 0; ni < 8; ni++) {
                const unsigned* r0 = Bd + (n0 + ni * 8) * SROW;
                b[ni][0] = r0[k0];
                b[ni][1] = r0[k0 + 4];
            }
#pragma unroll
            for (int mi = 0; mi < 4; mi++)
#pragma unroll
                for (int ni = 0; ni < 8; ni++) {
                    asm volatile(
                        "mma.sync.aligned.m16n8k8.row.col.f32.tf32.tf32.f32 "
                        "{%0,%1,%2,%3}, {%4,%5,%6,%7}, {%8,%9}, {%0,%1,%2,%3};"
                        : "+f"(acc[mi][ni][0]), "+f"(acc[mi][ni][1]),
                          "+f"(acc[mi][ni][2]), "+f"(acc[mi][ni][3])
                        : "r"(a[mi][0]), "r"(a[mi][1]), "r"(a[mi][2]),
                          "r"(a[mi][3]), "r"(b[ni][0]), "r"(b[ni][1]));
                }
        }
        __syncthreads();
    }

    // epilogue
#pragma unroll
    for (int ni = 0; ni < 8; ni++) {
        const int c = bn + wn * 64 + ni * 8 + t4 * 2;
        const float bb0 = bias[c];
        const float bb1 = bias[c + 1];
#pragma unroll
        for (int mi = 0; mi < 4; mi++) {
            const int r0 = bm + wm * 64 + mi * 16 + g;
            if (r0 < M)
                *(float2*)(C + (size_t)r0 * FD + c) =
                    make_float2(acc[mi][ni][0] + bb0, acc[mi][ni][1] + bb1);
            const int r1 = r0 + 8;
            if (r1 < M)
                *(float2*)(C + (size_t)r1 * FD + c) =
                    make_float2(acc[mi][ni][2] + bb0, acc[mi][ni][3] + bb1);
        }
    }
}

// ---------------------------------------------------------------------------
// kernel_launch
// ---------------------------------------------------------------------------
extern "C" void kernel_launch(void* const* d_in, const int* in_sizes, int n_in,
                              void* d_out, int out_size) {
    const float* x_paper   = (const float*)d_in[0];
    const float* x_dataset = (const float*)d_in[1];
    const int*   ei_pp     = (const int*)d_in[2];
    const int*   ei_pd     = (const int*)d_in[3];
    const int*   ei_dp     = (const int*)d_in[4];
    const float* Wl_pp = (const float*)d_in[5];
    const float* Wr_pp = (const float*)d_in[6];
    const float* b_pp  = (const float*)d_in[7];
    const float* Wl_pd = (const float*)d_in[8];
    const float* Wr_pd = (const float*)d_in[9];
    const float* b_pd  = (const float*)d_in[10];
    const float* Wl_dp = (const float*)d_in[11];
    const float* Wr_dp = (const float*)d_in[12];
    const float* b_dp  = (const float*)d_in[13];
    const float* Wdec_p = (const float*)d_in[14];
    const float* bdec_p = (const float*)d_in[15];
    const float* Wdec_d = (const float*)d_in[16];
    const float* bdec_d = (const float*)d_in[17];

    const int Epp = in_sizes[2] / 2;
    const int Epd = in_sizes[3] / 2;
    const int Edp = in_sizes[4] / 2;

    float* out = (float*)d_out;

    unsigned* base = nullptr;
    cudaGetSymbolAddress((void**)&base, g_scratch);
    float*    sum_pp = (float*)(base + U_SUM_PP);
    float*    sum_dp = (float*)(base + U_SUM_DP);
    float*    sum_pd = (float*)(base + U_SUM_PD);
    float*    cnt_pp = (float*)(base + U_CNT_PP);
    float*    cnt_dp = (float*)(base + U_CNT_DP);
    float*    cnt_pd = (float*)(base + U_CNT_PD);
    unsigned* xt_p   = base + U_XT_P;
    unsigned* xt_d   = base + U_XT_D;
    float*    rec_p  = (float*)(base + U_REC_P);
    float*    rec_d  = (float*)(base + U_REC_D);
    unsigned* xnt_p  = base + U_XNT_P;
    unsigned* xnt_d  = base + U_XNT_D;
    unsigned* wcomb  = base + U_WCOMB;
    unsigned* wrpp   = base + U_WRPP;
    unsigned* wrdp   = base + U_WRDP;
    unsigned* wrpd   = base + U_WRPD;
    unsigned* wlpd   = base + U_WLPD;
    unsigned* wdecp  = base + U_WDECP;
    unsigned* wdecd  = base + U_WDECD;
    float*    bsum   = (float*)(base + U_BSUM);

    const size_t smem_bytes = 2 * STAGE * sizeof(unsigned);
    cudaFuncSetAttribute(gemm_tc2, cudaFuncAttributeMaxDynamicSharedMemorySize,
                         (int)smem_bytes);

    // 1) zero sums + counts
    zero_kernel<<<4096, 256>>>((float4*)base, ZERO_END / 4);

    // 2) weight prep (tf32)
    addcvt_kernel<<<(FD * FD + 255) / 256, 256>>>(Wl_pp, Wl_dp, wcomb, FD * FD);
    cvt_kernel<<<(FD * FD / 4 + 255) / 256, 256>>>((const float4*)Wr_pp, (uint4*)wrpp, FD * FD / 4);
    cvt_kernel<<<(FD * FD / 4 + 255) / 256, 256>>>((const float4*)Wr_dp, (uint4*)wrdp, FD * FD / 4);
    cvt_kernel<<<(FD * FD / 4 + 255) / 256, 256>>>((const float4*)Wr_pd, (uint4*)wrpd, FD * FD / 4);
    cvt_kernel<<<(FD * FD / 4 + 255) / 256, 256>>>((const float4*)Wl_pd, (uint4*)wlpd, FD * FD / 4);
    cvt_kernel<<<(FD * 2 * FD / 4 + 255) / 256, 256>>>((const float4*)Wdec_p, (uint4*)wdecp, FD * 2 * FD / 4);
    cvt_kernel<<<(FD * 2 * FD / 4 + 255) / 256, 256>>>((const float4*)Wdec_d, (uint4*)wdecd, FD * 2 * FD / 4);
    addbias_kernel<<<2, 256>>>(b_pp, b_dp, bsum);

    // 3) scatter
    scatter_kernel<<<(Epp + 1) / 2, 256>>>(ei_pp, Epp, x_paper,   sum_pp, cnt_pp);
    scatter_kernel<<<(Edp + 1) / 2, 256>>>(ei_dp, Edp, x_dataset, sum_dp, cnt_dp);
    scatter_kernel<<<(Epd + 1) / 2, 256>>>(ei_pd, Epd, x_paper,   sum_pd, cnt_pd);

    // 4) finalize sums -> tf32 means (in place)
    finalize_kernel<<<(NP * (FD / 4) + 255) / 256, 256>>>((unsigned*)sum_pp, cnt_pp, NP);
    finalize_kernel<<<(NP * (FD / 4) + 255) / 256, 256>>>((unsigned*)sum_dp, cnt_dp, NP);
    finalize_kernel<<<(ND * (FD / 4) + 255) / 256, 256>>>((unsigned*)sum_pd, cnt_pd, ND);

    // 5) x -> tf32 (plain + normalized)
    cvtnorm_kernel<<<(NP * 32 + 255) / 256, 256>>>(x_paper, xnt_p, xt_p, NP);
    cvtnorm_kernel<<<(ND * 32 + 255) / 256, 256>>>(x_dataset, xnt_d, xt_d, ND);

    dim3 gp((NP + BM - 1) / BM, FD / BN);
    dim3 gd((ND + BM - 1) / BM, FD / BN);

    // 6) encoder GEMMs
    SegU sp = {};
    sp.A[0] = (unsigned*)sum_pp; sp.B[0] = wrpp;  sp.ldb[0] = FD;
    sp.A[1] = (unsigned*)sum_dp; sp.B[1] = wrdp;  sp.ldb[1] = FD;
    sp.A[2] = xt_p;              sp.B[2] = wcomb; sp.ldb[2] = FD;
    gemm_tc2<<<gp, 256, smem_bytes>>>(sp, 3, bsum, rec_p, NP);

    SegU sd = {};
    sd.A[0] = (unsigned*)sum_pd; sd.B[0] = wrpd; sd.ldb[0] = FD;
    sd.A[1] = xt_d;              sd.B[1] = wlpd; sd.ldb[1] = FD;
    gemm_tc2<<<gd, 256, smem_bytes>>>(sd, 2, b_pd, rec_d, ND);

    // 7) normalize rec -> tf32 (in place)
    cvtnorm_kernel<<<(NP * 32 + 255) / 256, 256>>>(rec_p, (unsigned*)rec_p, nullptr, NP);
    cvtnorm_kernel<<<(ND * 32 + 255) / 256, 256>>>(rec_d, (unsigned*)rec_d, nullptr, ND);

    // 8) decoder GEMMs
    SegU dpS = {};
    dpS.A[0] = (unsigned*)rec_p; dpS.B[0] = wdecp;      dpS.ldb[0] = 2 * FD;
    dpS.A[1] = xnt_p;            dpS.B[1] = wdecp + FD; dpS.ldb[1] = 2 * FD;
    gemm_tc2<<<gp, 256, smem_bytes>>>(dpS, 2, bdec_p, out, NP);

    SegU ddS = {};
    ddS.A[0] = (unsigned*)rec_d; ddS.B[0] = wdecd;      ddS.ldb[0] = 2 * FD;
    ddS.A[1] = xnt_d;            ddS.B[1] = wdecd + FD; ddS.ldb[1] = 2 * FD;
    gemm_tc2<<<gd, 256, smem_bytes>>>(ddS, 2, bdec_d, out + (size_t)NP * FD, ND);
}